// round 15
// baseline (speedup 1.0000x reference)
#include <cuda_runtime.h>
#include <cuda_bf16.h>
#include <cuda_fp16.h>
#include <cstdint>

#define DIM 256
#define N_NODES_MAX 50000
#define N_EDGES_MAX 800000
#define ELLW 96              // ELL row width (avg degree 16; P(>96) ~ 0)
#define OVF_CAP 4096

// ----- scratch (__device__ globals; no cudaMalloc allowed) -----
__device__ __half  g_hidden_h[N_NODES_MAX * DIM];     // x @ W (fp16)
__device__ __half  g_WT[DIM * DIM];                   // W^T fp16 (WT[n][k])
__device__ int     g_counts[N_NODES_MAX];             // per-row edge counts
__device__ int2    g_ell[(size_t)N_NODES_MAX * ELLW]; // (col, val-bits) per slot
__device__ int     g_ovf_cnt[1];
__device__ int4    g_ovf[OVF_CAP];                    // (row, col, val-bits, _)

// ===========================================================================
// Kernel 0: W^T fp16.  WT[n][k] = W[k][n]
// ===========================================================================
__global__ void wt_convert_kernel(const float* __restrict__ W,
                                  __half* __restrict__ wt) {
    int k = blockIdx.x;
    int n = threadIdx.x;
    wt[n * DIM + k] = __float2half_rn(W[k * DIM + n]);
}

// ===========================================================================
// Kernel 1: mma.sync fp16 GEMM with LDSM fragment loads.
// grid(4, M/128) single launch (x shared via L2), K-chunk 128.
// 256 thr = 8 warps (4Mx2N), CTA tile 128x64, warp tile 32x32, 2 CTAs/SM.
// Per K=16 step: 2 LDSM.x4 (A) + 2 LDSM.x4 (B) + 8 HMMA  (was 16 LDS + 8 HMMA).
// ===========================================================================
#define SA 136    // A smem row stride (128 + 8 pad) in halves; 272B = 16 mod 128
#define SB 264    // B smem row stride (256 + 8 pad) in halves; 528B = 16 mod 128
#define A_OFF 0
#define B_OFF (128 * SA)
#define GEMM_SMEM_BYTES ((128 * SA + 64 * SB) * 2)   // 68608

__device__ __forceinline__ void mma16816(float* c, const uint32_t* a, const uint32_t* b) {
    asm volatile(
        "mma.sync.aligned.m16n8k16.row.col.f32.f16.f16.f32 "
        "{%0,%1,%2,%3}, {%4,%5,%6,%7}, {%8,%9}, {%0,%1,%2,%3};"
        : "+f"(c[0]), "+f"(c[1]), "+f"(c[2]), "+f"(c[3])
        : "r"(a[0]), "r"(a[1]), "r"(a[2]), "r"(a[3]), "r"(b[0]), "r"(b[1]));
}

#define LDSM_X4(r0, r1, r2, r3, addr) \
    asm volatile("ldmatrix.sync.aligned.m8n8.x4.shared.b16 {%0,%1,%2,%3}, [%4];" \
                 : "=r"(r0), "=r"(r1), "=r"(r2), "=r"(r3) : "r"(addr))

__global__ __launch_bounds__(256, 2) void gemm_mma_kernel(
        const float* __restrict__ x,
        const __half* __restrict__ wt,
        __half* __restrict__ hidden, int M) {
    extern __shared__ __half sm[];

    const int tid  = threadIdx.x;
    const int warp = tid >> 5;
    const int lane = tid & 31;
    const int gid  = lane >> 2;
    const int tig  = lane & 3;
    const int wm   = warp >> 1;
    const int wn   = warp & 1;
    const int blockM = blockIdx.y * 128;
    const int blockN = blockIdx.x * 64;

    // ---- load B tile (full K): 64 rows x 256 k ----
#pragma unroll
    for (int t = 0; t < 8; t++) {
        int idx = tid + t * 256;
        int n = idx >> 5;
        int j = idx & 31;
        *reinterpret_cast<uint4*>(&sm[B_OFF + n * SB + j * 8]) =
            *reinterpret_cast<const uint4*>(&wt[(size_t)(blockN + n) * DIM + j * 8]);
    }

    // ---- per-lane LDSM base addresses (byte addresses in shared space) ----
    const uint32_t smem_u32 = (uint32_t)__cvta_generic_to_shared(sm);
    // A, per f: matrices {rows0-7,c0-7}{rows8-15,c0-7}{rows0-7,c8-15}{rows8-15,c8-15}
    //   lane row = (lane & 15); lanes >=16 take col-halves +8.
    uint32_t aAddr[2];
#pragma unroll
    for (int f = 0; f < 2; f++)
        aAddr[f] = smem_u32 + 2u * (uint32_t)(A_OFF +
                     (wm * 32 + f * 16 + (lane & 15)) * SA + ((lane >> 4) << 3));
    // B, per q (g-pair 2q,2q+1): matrices {g0,k0-7}{g0,k8-15}{g1,k0-7}{g1,k8-15}
    //   lane n-row = wn*32 + q*16 + (lane&7) + ((lane>>4)&1)*8 ; k-halves +8 if (lane&8)
    uint32_t bAddr[2];
#pragma unroll
    for (int q = 0; q < 2; q++)
        bAddr[q] = smem_u32 + 2u * (uint32_t)(B_OFF +
                     (wn * 32 + q * 16 + (lane & 7) + ((lane >> 4) & 1) * 8) * SB +
                     ((lane >> 3) & 1) * 8);

    float c[2][4][4];
#pragma unroll
    for (int f = 0; f < 2; f++)
#pragma unroll
        for (int g = 0; g < 4; g++)
#pragma unroll
            for (int q = 0; q < 4; q++) c[f][g][q] = 0.f;

    for (int kc = 0; kc < 2; kc++) {          // two K=128 chunks
        __syncthreads();
        // ---- stage A chunk: x[blockM..+128, kc*128..+128] fp32 -> fp16 ----
#pragma unroll
        for (int t = 0; t < 16; t++) {
            int idx = tid + t * 256;          // 0..4095 float4 slots
            int row = idx >> 5;               // 0..127
            int c4  = idx & 31;               // float4 within 128-col chunk
            float4 v = make_float4(0.f, 0.f, 0.f, 0.f);
            if (blockM + row < M)
                v = *reinterpret_cast<const float4*>(
                        &x[(size_t)(blockM + row) * DIM + kc * 128 + c4 * 4]);
            __half2 p0 = __floats2half2_rn(v.x, v.y);
            __half2 p1 = __floats2half2_rn(v.z, v.w);
            *reinterpret_cast<uint2*>(&sm[A_OFF + row * SA + c4 * 4]) =
                make_uint2(*reinterpret_cast<uint32_t*>(&p0),
                           *reinterpret_cast<uint32_t*>(&p1));
        }
        __syncthreads();

#pragma unroll
        for (int ks = 0; ks < 8; ks++) {      // eight K=16 steps per chunk
            const int kb = ks * 16;
            uint32_t a[2][4], bb[4][2];
            LDSM_X4(a[0][0], a[0][1], a[0][2], a[0][3], aAddr[0] + 2 * kb);
            LDSM_X4(a[1][0], a[1][1], a[1][2], a[1][3], aAddr[1] + 2 * kb);
            LDSM_X4(bb[0][0], bb[0][1], bb[1][0], bb[1][1],
                    bAddr[0] + 2 * (kc * 128 + kb));
            LDSM_X4(bb[2][0], bb[2][1], bb[3][0], bb[3][1],
                    bAddr[1] + 2 * (kc * 128 + kb));
#pragma unroll
            for (int f = 0; f < 2; f++)
#pragma unroll
                for (int g = 0; g < 4; g++)
                    mma16816(c[f][g], a[f], bb[g]);
        }
    }

#pragma unroll
    for (int f = 0; f < 2; f++) {
#pragma unroll
        for (int g = 0; g < 4; g++) {
            int row = blockM + wm * 32 + f * 16 + gid;
            int col = blockN + wn * 32 + g * 8 + 2 * tig;
            if (row < M)
                *reinterpret_cast<__half2*>(&hidden[(size_t)row * DIM + col]) =
                    __floats2half2_rn(c[f][g][0], c[f][g][1]);
            if (row + 8 < M)
                *reinterpret_cast<__half2*>(&hidden[(size_t)(row + 8) * DIM + col]) =
                    __floats2half2_rn(c[f][g][2], c[f][g][3]);
        }
    }
}

// ===========================================================================
// ELL build: ONE scatter kernel.
// ===========================================================================
__global__ void ell_scatter_kernel(const int* __restrict__ rows,
                                   const int* __restrict__ cols,
                                   const float* __restrict__ vals,
                                   int*  __restrict__ counts,
                                   int2* __restrict__ ell,
                                   int*  __restrict__ ovf_cnt,
                                   int4* __restrict__ ovf,
                                   int E) {
    int i = blockIdx.x * blockDim.x + threadIdx.x;
    if (i < E) {
        int r   = rows[i];
        int pos = atomicAdd(&counts[r], 1);
        if (pos < ELLW) {
            ell[(size_t)r * ELLW + pos] = make_int2(cols[i], __float_as_int(vals[i]));
        } else {
            int o = atomicAdd(ovf_cnt, 1);
            if (o < OVF_CAP)
                ovf[o] = make_int4(r, cols[i], __float_as_int(vals[i]), 0);
        }
    }
}

// ===========================================================================
// SpMM (R11 scalar form — measured 40.7us): warp per dest row,
// lane owns 8 dims (one uint4 gather per edge), 8-edge unroll.
// ===========================================================================
__device__ __forceinline__ void fma8_half(float* acc, uint4 r, float v) {
    float2 f0 = __half22float2(*reinterpret_cast<__half2*>(&r.x));
    float2 f1 = __half22float2(*reinterpret_cast<__half2*>(&r.y));
    float2 f2 = __half22float2(*reinterpret_cast<__half2*>(&r.z));
    float2 f3 = __half22float2(*reinterpret_cast<__half2*>(&r.w));
    acc[0] = fmaf(v, f0.x, acc[0]); acc[1] = fmaf(v, f0.y, acc[1]);
    acc[2] = fmaf(v, f1.x, acc[2]); acc[3] = fmaf(v, f1.y, acc[3]);
    acc[4] = fmaf(v, f2.x, acc[4]); acc[5] = fmaf(v, f2.y, acc[5]);
    acc[6] = fmaf(v, f3.x, acc[6]); acc[7] = fmaf(v, f3.y, acc[7]);
}

__global__ __launch_bounds__(256) void spmm_ell_kernel(const int*  __restrict__ counts,
                                                       const int2* __restrict__ ell,
                                                       const __half* __restrict__ hidden,
                                                       const float* __restrict__ b,
                                                       float*       __restrict__ out,
                                                       int M) {
    const int w    = (blockIdx.x * blockDim.x + threadIdx.x) >> 5;
    const int lane = threadIdx.x & 31;
    if (w >= M) return;

    const int cnt = min(counts[w], ELLW);
    const int2* erow = ell + (size_t)w * ELLW;

    float acc[8];
#pragma unroll
    for (int q = 0; q < 8; q++) acc[q] = 0.f;
    const __half* hbase = hidden + lane * 8;

    int j = 0;
    for (; j + 7 < cnt; j += 8) {
        int2 p[8];
#pragma unroll
        for (int q = 0; q < 8; q++) p[q] = erow[j + q];
        uint4 r[8];
#pragma unroll
        for (int q = 0; q < 8; q++)
            r[q] = *reinterpret_cast<const uint4*>(hbase + (size_t)p[q].x * DIM);
#pragma unroll
        for (int q = 0; q < 8; q++)
            fma8_half(acc, r[q], __int_as_float(p[q].y));
    }
    for (; j + 3 < cnt; j += 4) {
        int2 p[4];
#pragma unroll
        for (int q = 0; q < 4; q++) p[q] = erow[j + q];
        uint4 r[4];
#pragma unroll
        for (int q = 0; q < 4; q++)
            r[q] = *reinterpret_cast<const uint4*>(hbase + (size_t)p[q].x * DIM);
#pragma unroll
        for (int q = 0; q < 4; q++)
            fma8_half(acc, r[q], __int_as_float(p[q].y));
    }
    for (; j < cnt; j++) {
        int2 p0 = erow[j];
        uint4 r0 = *reinterpret_cast<const uint4*>(hbase + (size_t)p0.x * DIM);
        fma8_half(acc, r0, __int_as_float(p0.y));
    }

    const float4* b4 = reinterpret_cast<const float4*>(b + lane * 8);
    float4 bb0 = b4[0], bb1 = b4[1];
    float4* o = reinterpret_cast<float4*>(out + (size_t)w * DIM + lane * 8);
    o[0] = make_float4(acc[0] + bb0.x, acc[1] + bb0.y, acc[2] + bb0.z, acc[3] + bb0.w);
    o[1] = make_float4(acc[4] + bb1.x, acc[5] + bb1.y, acc[6] + bb1.z, acc[7] + bb1.w);
}

// ===========================================================================
// Overflow fixup: normally n==0.
// ===========================================================================
__global__ void ovf_fixup_kernel(const int* __restrict__ ovf_cnt,
                                 const int4* __restrict__ ovf,
                                 const __half* __restrict__ hidden,
                                 float* __restrict__ out) {
    int n = min(*ovf_cnt, OVF_CAP);
    int t = threadIdx.x;
    for (int e = 0; e < n; e++) {
        int4 p = ovf[e];
        float v = __int_as_float(p.z);
        out[(size_t)p.x * DIM + t] =
            fmaf(v, __half2float(hidden[(size_t)p.y * DIM + t]),
                 out[(size_t)p.x * DIM + t]);
    }
}

// ===========================================================================
// Launch (unchanged structure):
//   s_csr  : memsets -> ell_scatter        (|| gemm)
//   default: wt -> gemm (grid 4x391) -> [wait ELL] spmm -> fixup
// ===========================================================================
extern "C" void kernel_launch(void* const* d_in, const int* in_sizes, int n_in,
                              void* d_out, int out_size) {
    const float* x        = (const float*)d_in[0];
    const int*   adj_rows = (const int*)  d_in[1];
    const int*   adj_cols = (const int*)  d_in[2];
    const float* adj_vals = (const float*)d_in[3];
    const float* W        = (const float*)d_in[4];
    const float* b        = (const float*)d_in[5];
    float*       out      = (float*)d_out;

    const int M = in_sizes[0] / DIM;   // 50000
    const int E = in_sizes[1];         // 800000

    __half *hidden, *wt;
    int *counts, *ovf_cnt;
    int2 *ell;
    int4 *ovf;
    cudaGetSymbolAddress((void**)&hidden,  g_hidden_h);
    cudaGetSymbolAddress((void**)&wt,      g_WT);
    cudaGetSymbolAddress((void**)&counts,  g_counts);
    cudaGetSymbolAddress((void**)&ell,     g_ell);
    cudaGetSymbolAddress((void**)&ovf_cnt, g_ovf_cnt);
    cudaGetSymbolAddress((void**)&ovf,     g_ovf);

    static cudaStream_t s_csr = nullptr;
    static cudaEvent_t  ev_fork = nullptr, ev_csr = nullptr;
    if (s_csr == nullptr) {
        cudaStreamCreateWithFlags(&s_csr, cudaStreamNonBlocking);
        cudaEventCreateWithFlags(&ev_fork, cudaEventDisableTiming);
        cudaEventCreateWithFlags(&ev_csr,  cudaEventDisableTiming);
        cudaFuncSetAttribute(gemm_mma_kernel,
                             cudaFuncAttributeMaxDynamicSharedMemorySize, GEMM_SMEM_BYTES);
    }

    // ---- fork: ELL build on s_csr ----
    cudaEventRecord(ev_fork, 0);
    cudaStreamWaitEvent(s_csr, ev_fork, 0);

    cudaMemsetAsync(counts, 0, (size_t)M * sizeof(int), s_csr);
    cudaMemsetAsync(ovf_cnt, 0, sizeof(int), s_csr);
    ell_scatter_kernel<<<(E + 255) / 256, 256, 0, s_csr>>>(adj_rows, adj_cols, adj_vals,
                                                           counts, ell, ovf_cnt, ovf, E);
    cudaEventRecord(ev_csr, s_csr);

    // ---- GEMM (single launch, 4 N-blocks co-resident, x shared via L2) ----
    wt_convert_kernel<<<DIM, DIM>>>(W, wt);
    dim3 gemmGrid(4, (M + 127) / 128);
    gemm_mma_kernel<<<gemmGrid, 256, GEMM_SMEM_BYTES>>>(x, wt, hidden, M);

    // ---- SpMM after GEMM + ELL ----
    cudaStreamWaitEvent(0, ev_csr, 0);
    spmm_ell_kernel<<<(M * 32 + 255) / 256, 256>>>(counts, ell, hidden, b, out, M);
    ovf_fixup_kernel<<<1, 256>>>(ovf_cnt, ovf, hidden, out);
}